// round 1
// baseline (speedup 1.0000x reference)
#include <cuda_runtime.h>
#include <cstdint>
#include <math.h>

#define D_MODEL 1024
#define D_STATE 16
#define D_CONV  4
#define D_INNER 2048
#define DT_RANK 64
#define BATCH   4
#define SEQLEN  2048
#define ROWS    (BATCH * SEQLEN)   // 8192

// ---------------- device scratch (allocation-free rule: __device__ globals) ----
__device__ __align__(16) float g_u[ROWS * D_INNER];      // pre-conv u
__device__ __align__(16) float g_z[ROWS * D_INNER];      // gate
__device__ __align__(16) float g_uc[ROWS * D_INNER];     // conv+silu(u)
__device__ __align__(16) float g_delta[ROWS * D_INNER];  // softplus(dt)
__device__ __align__(16) float g_y[ROWS * D_INNER];      // scan out * silu(z)
__device__ __align__(16) float g_dtr[ROWS * DT_RANK];
__device__ __align__(16) float g_Bm[ROWS * D_STATE];
__device__ __align__(16) float g_Cm[ROWS * D_STATE];

// ---------------- generic tiled SGEMM, A[MxK] row-major, B[KxN] row-major -----
enum { EPI_PLAIN = 0, EPI_SPLIT = 1, EPI_SOFTPLUS = 2 };

template <int BM, int BN, int BK, int TM, int TN, int EPI>
__global__ __launch_bounds__((BM / TM) * (BN / TN))
void sgemm_kernel(int M, int N, int K,
                  const float* __restrict__ A, const float* __restrict__ B,
                  float* __restrict__ O0, float* __restrict__ O1,
                  const float* __restrict__ bias)
{
    constexpr int NT = (BM / TM) * (BN / TN);
    const int cRow = blockIdx.y;
    const int cCol = blockIdx.x;
    const int tid  = threadIdx.x;

    __shared__ float As[BK][BM];
    __shared__ float Bs[BK][BN];

    const int tCol = tid % (BN / TN);
    const int tRow = tid / (BN / TN);

    A += (size_t)cRow * BM * K;
    B += (size_t)cCol * BN;

    // A loads: float4 along K
    const int aRow = tid / (BK / 4);
    const int aCol = (tid % (BK / 4)) * 4;
    constexpr int aRowStride = NT / (BK / 4);
    // B loads: float4 along N
    const int bRow = tid / (BN / 4);
    const int bCol = (tid % (BN / 4)) * 4;
    constexpr int bRowStride = NT / (BN / 4);

    float acc[TM][TN] = {};
    float rM[TM], rN[TN];

    for (int k0 = 0; k0 < K; k0 += BK) {
        #pragma unroll
        for (int r = 0; r < BM; r += aRowStride) {
            float4 v = *(const float4*)&A[(size_t)(aRow + r) * K + k0 + aCol];
            As[aCol + 0][aRow + r] = v.x;
            As[aCol + 1][aRow + r] = v.y;
            As[aCol + 2][aRow + r] = v.z;
            As[aCol + 3][aRow + r] = v.w;
        }
        #pragma unroll
        for (int r = 0; r < BK; r += bRowStride) {
            *(float4*)&Bs[bRow + r][bCol] =
                *(const float4*)&B[(size_t)(k0 + bRow + r) * N + bCol];
        }
        __syncthreads();

        #pragma unroll
        for (int kk = 0; kk < BK; ++kk) {
            #pragma unroll
            for (int i = 0; i < TM; ++i) rM[i] = As[kk][tRow * TM + i];
            #pragma unroll
            for (int j = 0; j < TN; ++j) rN[j] = Bs[kk][tCol * TN + j];
            #pragma unroll
            for (int i = 0; i < TM; ++i)
                #pragma unroll
                for (int j = 0; j < TN; ++j)
                    acc[i][j] = fmaf(rM[i], rN[j], acc[i][j]);
        }
        __syncthreads();
    }

    #pragma unroll
    for (int i = 0; i < TM; ++i) {
        const int row = cRow * BM + tRow * TM + i;
        #pragma unroll
        for (int j = 0; j < TN; j += 4) {
            const int col = cCol * BN + tCol * TN + j;
            if (EPI == EPI_PLAIN) {
                float4 v = {acc[i][j], acc[i][j + 1], acc[i][j + 2], acc[i][j + 3]};
                *(float4*)&O0[(size_t)row * N + col] = v;
            } else if (EPI == EPI_SPLIT) {
                float4 v = {acc[i][j], acc[i][j + 1], acc[i][j + 2], acc[i][j + 3]};
                const int H = N / 2;
                if (col < H) *(float4*)&O0[(size_t)row * H + col] = v;
                else         *(float4*)&O1[(size_t)row * H + (col - H)] = v;
            } else { // EPI_SOFTPLUS
                #pragma unroll
                for (int jj = 0; jj < 4; ++jj) {
                    float v = acc[i][j + jj] + bias[col + jj];
                    v = (v > 20.0f) ? v : log1pf(__expf(v));
                    O0[(size_t)row * N + col + jj] = v;
                }
            }
        }
    }
}

// ---------------- special GEMM for x-proj: M=8192, N=96, K=2048 ---------------
__global__ __launch_bounds__(256)
void sgemm96_kernel(const float* __restrict__ A, const float* __restrict__ B,
                    float* __restrict__ dtr, float* __restrict__ Bm,
                    float* __restrict__ Cm)
{
    constexpr int BM = 64, BN = 96, BK = 16, TM = 4, TN = 6;
    const int K = D_INNER, N = BN;
    const int cRow = blockIdx.x;
    const int tid = threadIdx.x;

    __shared__ float As[BK][BM];
    __shared__ float Bs[BK][BN];

    const int tCol = tid % (BN / TN);  // 16
    const int tRow = tid / (BN / TN);  // 16

    A += (size_t)cRow * BM * K;

    const int aRow = tid / 4;
    const int aCol = (tid % 4) * 4;

    float acc[TM][TN] = {};
    float rM[TM], rN[TN];

    for (int k0 = 0; k0 < K; k0 += BK) {
        {
            float4 v = *(const float4*)&A[(size_t)aRow * K + k0 + aCol];
            As[aCol + 0][aRow] = v.x;
            As[aCol + 1][aRow] = v.y;
            As[aCol + 2][aRow] = v.z;
            As[aCol + 3][aRow] = v.w;
        }
        #pragma unroll
        for (int idx = tid; idx < BK * BN; idx += 256) {
            int r = idx / BN, c = idx % BN;
            Bs[r][c] = B[(size_t)(k0 + r) * N + c];
        }
        __syncthreads();

        #pragma unroll
        for (int kk = 0; kk < BK; ++kk) {
            #pragma unroll
            for (int i = 0; i < TM; ++i) rM[i] = As[kk][tRow * TM + i];
            #pragma unroll
            for (int j = 0; j < TN; ++j) rN[j] = Bs[kk][tCol * TN + j];
            #pragma unroll
            for (int i = 0; i < TM; ++i)
                #pragma unroll
                for (int j = 0; j < TN; ++j)
                    acc[i][j] = fmaf(rM[i], rN[j], acc[i][j]);
        }
        __syncthreads();
    }

    #pragma unroll
    for (int i = 0; i < TM; ++i) {
        const int row = cRow * BM + tRow * TM + i;
        #pragma unroll
        for (int j = 0; j < TN; ++j) {
            const int col = tCol * TN + j;
            float v = acc[i][j];
            if (col < DT_RANK)                 g_dtr[(size_t)row * DT_RANK + col] = v;
            else if (col < DT_RANK + D_STATE)  g_Bm[(size_t)row * D_STATE + (col - DT_RANK)] = v;
            else                               g_Cm[(size_t)row * D_STATE + (col - DT_RANK - D_STATE)] = v;
        }
    }
}

// ---------------- causal depthwise conv (k=4) + SiLU --------------------------
__global__ __launch_bounds__(256)
void conv_silu_kernel(const float* __restrict__ u, const float* __restrict__ w,
                      const float* __restrict__ bias, float* __restrict__ uc)
{
    constexpr int CHUNK = 16;
    int gid = blockIdx.x * blockDim.x + threadIdx.x;
    // layout: d fastest for coalescing
    int d = gid & (D_INNER - 1);
    int rest = gid >> 11;
    int b = rest & (BATCH - 1);
    int chunk = rest >> 2;
    int l0 = chunk * CHUNK;

    const float w0 = w[d * 4 + 0], w1 = w[d * 4 + 1],
                w2 = w[d * 4 + 2], w3 = w[d * 4 + 3];
    const float bb = bias[d];

    const size_t base = ((size_t)b * SEQLEN + l0) * D_INNER + d;
    const float* up = u + base;
    float* op = uc + base;

    float xm3, xm2, xm1;
    if (l0 == 0) { xm3 = 0.f; xm2 = 0.f; xm1 = 0.f; }
    else {
        xm3 = up[-3 * D_INNER];
        xm2 = up[-2 * D_INNER];
        xm1 = up[-1 * D_INNER];
    }
    #pragma unroll
    for (int i = 0; i < CHUNK; ++i) {
        float cur = up[(size_t)i * D_INNER];
        float v = fmaf(xm3, w0, fmaf(xm2, w1, fmaf(xm1, w2, fmaf(cur, w3, bb))));
        float s = v / (1.0f + __expf(-v));   // silu
        op[(size_t)i * D_INNER] = s;
        xm3 = xm2; xm2 = xm1; xm1 = cur;
    }
}

// ---------------- selective scan: 4 threads per (b,d) channel -----------------
__global__ __launch_bounds__(128)
void scan_kernel(const float* __restrict__ delta, const float* __restrict__ u,
                 const float* __restrict__ z, const float* __restrict__ Bm,
                 const float* __restrict__ Cm, const float* __restrict__ A_log,
                 const float* __restrict__ Dp, float* __restrict__ y)
{
    const int t = blockIdx.x * blockDim.x + threadIdx.x;  // 32768 threads
    const int sub = t & 3;
    const int ch = t >> 2;            // (b,d) channel, 0..8191
    const int d = ch & (D_INNER - 1);
    const int b = ch >> 11;
    const int n0 = sub * 4;           // first state index of this thread

    const float a0 = -__expf(A_log[d * D_STATE + n0 + 0]);
    const float a1 = -__expf(A_log[d * D_STATE + n0 + 1]);
    const float a2 = -__expf(A_log[d * D_STATE + n0 + 2]);
    const float a3 = -__expf(A_log[d * D_STATE + n0 + 3]);

    const bool fast =
        fabsf(a0 + (float)(n0 + 1)) < 1e-3f * (n0 + 1) &&
        fabsf(a1 + (float)(n0 + 2)) < 1e-3f * (n0 + 2) &&
        fabsf(a2 + (float)(n0 + 3)) < 1e-3f * (n0 + 3) &&
        fabsf(a3 + (float)(n0 + 4)) < 1e-3f * (n0 + 4);

    const size_t base = (size_t)b * SEQLEN * D_INNER + d;
    const float* dp = delta + base;
    const float* up = u + base;
    const float* zp = z + base;
    float* yp = y + base;
    const float4* Bp = (const float4*)Bm + (size_t)b * SEQLEN * 4 + sub;
    const float4* Cp = (const float4*)Cm + (size_t)b * SEQLEN * 4 + sub;
    const float Dd = Dp[d];

    float h0 = 0.f, h1 = 0.f, h2 = 0.f, h3 = 0.f;

    if (fast) {
        #pragma unroll 2
        for (int l = 0; l < SEQLEN; ++l) {
            const float dt = dp[(size_t)l * D_INNER];
            const float uu = up[(size_t)l * D_INNER];
            const float4 Bv = Bp[(size_t)l * 4];
            const float4 Cv = Cp[(size_t)l * 4];
            const float e  = __expf(-dt);
            const float e2 = e * e;
            const float e4 = e2 * e2;
            const float e8 = e4 * e4;
            float m = 1.f;
            if (sub & 1) m = e4;
            if (sub & 2) m *= e8;
            const float dA0 = m * e;
            const float dA1 = dA0 * e;
            const float dA2 = dA1 * e;
            const float dA3 = dA2 * e;
            const float xv = dt * uu;
            h0 = fmaf(h0, dA0, xv * Bv.x);
            h1 = fmaf(h1, dA1, xv * Bv.y);
            h2 = fmaf(h2, dA2, xv * Bv.z);
            h3 = fmaf(h3, dA3, xv * Bv.w);
            float yv = h0 * Cv.x + h1 * Cv.y + h2 * Cv.z + h3 * Cv.w;
            yv += __shfl_xor_sync(0xffffffffu, yv, 1);
            yv += __shfl_xor_sync(0xffffffffu, yv, 2);
            if (sub == 0) {
                const float zz = zp[(size_t)l * D_INNER];
                const float sz = zz / (1.0f + __expf(-zz));
                yp[(size_t)l * D_INNER] = (yv + uu * Dd) * sz;
            }
        }
    } else {
        #pragma unroll 2
        for (int l = 0; l < SEQLEN; ++l) {
            const float dt = dp[(size_t)l * D_INNER];
            const float uu = up[(size_t)l * D_INNER];
            const float4 Bv = Bp[(size_t)l * 4];
            const float4 Cv = Cp[(size_t)l * 4];
            const float dA0 = __expf(dt * a0);
            const float dA1 = __expf(dt * a1);
            const float dA2 = __expf(dt * a2);
            const float dA3 = __expf(dt * a3);
            const float xv = dt * uu;
            h0 = fmaf(h0, dA0, xv * Bv.x);
            h1 = fmaf(h1, dA1, xv * Bv.y);
            h2 = fmaf(h2, dA2, xv * Bv.z);
            h3 = fmaf(h3, dA3, xv * Bv.w);
            float yv = h0 * Cv.x + h1 * Cv.y + h2 * Cv.z + h3 * Cv.w;
            yv += __shfl_xor_sync(0xffffffffu, yv, 1);
            yv += __shfl_xor_sync(0xffffffffu, yv, 2);
            if (sub == 0) {
                const float zz = zp[(size_t)l * D_INNER];
                const float sz = zz / (1.0f + __expf(-zz));
                yp[(size_t)l * D_INNER] = (yv + uu * Dd) * sz;
            }
        }
    }
}

// ---------------- launch ------------------------------------------------------
extern "C" void kernel_launch(void* const* d_in, const int* in_sizes, int n_in,
                              void* d_out, int out_size)
{
    const float* x      = (const float*)d_in[0];
    const float* W_in   = (const float*)d_in[1];
    const float* conv_w = (const float*)d_in[2];
    const float* conv_b = (const float*)d_in[3];
    const float* W_xprj = (const float*)d_in[4];
    const float* W_dt   = (const float*)d_in[5];
    const float* b_dt   = (const float*)d_in[6];
    const float* A_log  = (const float*)d_in[7];
    const float* Dp     = (const float*)d_in[8];
    const float* W_out  = (const float*)d_in[9];
    float* out = (float*)d_out;

    float *u, *z, *uc, *delta, *yb, *dtr, *Bm, *Cm;
    cudaGetSymbolAddress((void**)&u,     g_u);
    cudaGetSymbolAddress((void**)&z,     g_z);
    cudaGetSymbolAddress((void**)&uc,    g_uc);
    cudaGetSymbolAddress((void**)&delta, g_delta);
    cudaGetSymbolAddress((void**)&yb,    g_y);
    cudaGetSymbolAddress((void**)&dtr,   g_dtr);
    cudaGetSymbolAddress((void**)&Bm,    g_Bm);
    cudaGetSymbolAddress((void**)&Cm,    g_Cm);

    // G1: xz = x @ W_in, split into u | z
    sgemm_kernel<128, 128, 8, 8, 8, EPI_SPLIT>
        <<<dim3(2 * D_INNER / 128, ROWS / 128), 256>>>(
            ROWS, 2 * D_INNER, D_MODEL, x, W_in, u, z, nullptr);

    // conv + silu
    {
        int total = BATCH * D_INNER * (SEQLEN / 16);
        conv_silu_kernel<<<total / 256, 256>>>(u, conv_w, conv_b, uc);
    }

    // G2: proj = uc @ W_xproj -> dtr | Bm | Cm
    sgemm96_kernel<<<ROWS / 64, 256>>>(uc, W_xprj, dtr, Bm, Cm);

    // G3: delta = softplus(dtr @ W_dt + b_dt)
    sgemm_kernel<128, 128, 8, 8, 8, EPI_SOFTPLUS>
        <<<dim3(D_INNER / 128, ROWS / 128), 256>>>(
            ROWS, D_INNER, DT_RANK, dtr, W_dt, delta, nullptr, b_dt);

    // scan + gating
    scan_kernel<<<(ROWS * 4) / 128, 128>>>(delta, uc, z, Bm, Cm, A_log, Dp, yb);

    // G5: out = y @ W_out
    sgemm_kernel<128, 128, 8, 8, 8, EPI_PLAIN>
        <<<dim3(D_MODEL / 128, ROWS / 128), 256>>>(
            ROWS, D_MODEL, D_INNER, yb, W_out, out, nullptr, nullptr);
}

// round 3
// speedup vs baseline: 1.4406x; 1.4406x over previous
#include <cuda_runtime.h>
#include <cuda_bf16.h>
#include <cstdint>
#include <math.h>

#define D_MODEL 1024
#define D_STATE 16
#define D_INNER 2048
#define DT_RANK 64
#define BATCH   4
#define SEQLEN  2048
#define ROWS    (BATCH * SEQLEN)   // 8192

// ---------------- device scratch (allocation-free rule) -----------------------
__device__ __align__(16) float g_u[ROWS * D_INNER];
__device__ __align__(16) float g_z[ROWS * D_INNER];
__device__ __align__(16) float g_uc[ROWS * D_INNER];
__device__ __align__(16) float g_delta[ROWS * D_INNER];
__device__ __align__(16) float g_y[ROWS * D_INNER];
__device__ __align__(16) float g_dtr[ROWS * DT_RANK];
__device__ __align__(16) float g_Bm[ROWS * D_STATE];
__device__ __align__(16) float g_Cm[ROWS * D_STATE];

// packed bf16 operands (hi|hi|lo along K for A; hi|lo|hi for B^T)
__device__ __align__(16) __nv_bfloat16 g_x2  [ROWS * 3 * D_MODEL];
__device__ __align__(16) __nv_bfloat16 g_Win2[(2*D_INNER) * 3 * D_MODEL];
__device__ __align__(16) __nv_bfloat16 g_uc2 [ROWS * 3 * D_INNER];
__device__ __align__(16) __nv_bfloat16 g_Wxp2[128 * 3 * D_INNER];
__device__ __align__(16) __nv_bfloat16 g_dtr2[ROWS * 3 * DT_RANK];
__device__ __align__(16) __nv_bfloat16 g_Wdt2[D_INNER * 3 * DT_RANK];
__device__ __align__(16) __nv_bfloat16 g_y2  [ROWS * 3 * D_INNER];
__device__ __align__(16) __nv_bfloat16 g_Wout2[D_MODEL * 3 * D_INNER];

// ---------------- helpers -----------------------------------------------------
__device__ __forceinline__ uint32_t smem_u32(const void* p) {
    uint32_t a;
    asm("{ .reg .u64 t; cvta.to.shared.u64 t, %1; cvt.u32.u64 %0, t; }" : "=r"(a) : "l"(p));
    return a;
}
__device__ __forceinline__ void cp16(uint32_t saddr, const void* gaddr) {
    asm volatile("cp.async.cg.shared.global [%0], [%1], 16;" :: "r"(saddr), "l"(gaddr));
}
#define SWZ(o) ((o) ^ ((((uint32_t)(o)) >> 3) & 0x70))

__device__ __forceinline__ void ldm_x4(uint32_t& r0, uint32_t& r1, uint32_t& r2, uint32_t& r3,
                                       uint32_t addr) {
    asm volatile("ldmatrix.sync.aligned.m8n8.x4.shared.b16 {%0,%1,%2,%3}, [%4];"
                 : "=r"(r0), "=r"(r1), "=r"(r2), "=r"(r3) : "r"(addr));
}
__device__ __forceinline__ void mma16816(float& c0, float& c1, float& c2, float& c3,
                                         uint32_t a0, uint32_t a1, uint32_t a2, uint32_t a3,
                                         uint32_t b0, uint32_t b1) {
    asm volatile("mma.sync.aligned.m16n8k16.row.col.f32.bf16.bf16.f32 "
                 "{%0,%1,%2,%3}, {%4,%5,%6,%7}, {%8,%9}, {%0,%1,%2,%3};"
                 : "+f"(c0), "+f"(c1), "+f"(c2), "+f"(c3)
                 : "r"(a0), "r"(a1), "r"(a2), "r"(a3), "r"(b0), "r"(b1));
}

// ---------------- bf16 mma.sync GEMM ------------------------------------------
// C[M,N] = A[M,Kp] * Bt[N,Kp]^T, both bf16 K-major row-major, fp32 accumulate.
// BM=BN=128, BK=64 (128B rows, xor-swizzled), 4-stage cp.async pipeline,
// 256 threads = 8 warps in 4(m) x 2(n), warp tile 32x64.
enum { EPI_PLAIN = 0, EPI_SPLIT = 1, EPI_SOFTPLUS = 2, EPI_XPROJ = 3 };

#define GBM 128
#define GBN 128
#define GBK 64
#define GSTAGES 4
#define GTILE_B (GBM * GBK * 2)          // 16384 bytes per operand tile
#define GSTAGE_B (2 * GTILE_B)           // 32768
#define GEMM_SMEM (GSTAGES * GSTAGE_B)   // 131072

template <int EPI>
__global__ __launch_bounds__(256, 1)
void gemm_tc(const __nv_bfloat16* __restrict__ A, const __nv_bfloat16* __restrict__ Bt,
             int Kp, int N,
             float* __restrict__ O0, float* __restrict__ O1, float* __restrict__ O2,
             const float* __restrict__ bias)
{
    extern __shared__ char smem[];
    const uint32_t sb = smem_u32(smem);
    const int tid = threadIdx.x;
    const int wid = tid >> 5, lid = tid & 31;
    const int wr = wid & 3;          // warp m index (0..3) -> rows 32*wr
    const int wc = wid >> 2;         // warp n index (0..1) -> cols 64*wc
    const int m0 = blockIdx.y * GBM;
    const int n0 = blockIdx.x * GBN;
    const int chunks = Kp / GBK;

    const __nv_bfloat16* Ap = A + (size_t)m0 * Kp;
    const __nv_bfloat16* Bp = Bt + (size_t)n0 * Kp;

    // cp.async mapping: 256 threads cover 32 rows x 8 chunks per step, 4 steps
    const int ldrow = tid >> 3;
    const int ldch  = tid & 7;

    auto load_stage = [&](int c) {
        const int s = c & (GSTAGES - 1);
        const uint32_t sa = sb + s * GSTAGE_B;
        const uint32_t sB = sa + GTILE_B;
        const int k0 = c * GBK;
        #pragma unroll
        for (int j = 0; j < 4; ++j) {
            const int r = ldrow + j * 32;
            const uint32_t so = SWZ(r * 128 + ldch * 16);
            cp16(sa + so, Ap + (size_t)r * Kp + k0 + ldch * 8);
            cp16(sB + so, Bp + (size_t)r * Kp + k0 + ldch * 8);
        }
        asm volatile("cp.async.commit_group;" ::: "memory");
    };

    const int pre = (chunks < GSTAGES - 1) ? chunks : (GSTAGES - 1);
    for (int c = 0; c < pre; ++c) load_stage(c);

    float acc[2][8][4];
    #pragma unroll
    for (int i = 0; i < 2; ++i)
        #pragma unroll
        for (int j = 0; j < 8; ++j)
            #pragma unroll
            for (int k = 0; k < 4; ++k) acc[i][j][k] = 0.f;

    // ldmatrix per-lane source row/chunk-half
    const int lrow = lid & 15;         // row within 16
    const int lhalf = lid >> 4;        // which 16B chunk (k half)

    for (int c = 0; c < chunks; ++c) {
        const int remaining = chunks - 1 - c;
        if (remaining >= 2)      asm volatile("cp.async.wait_group 2;" ::: "memory");
        else if (remaining == 1) asm volatile("cp.async.wait_group 1;" ::: "memory");
        else                     asm volatile("cp.async.wait_group 0;" ::: "memory");
        __syncthreads();

        if (c + GSTAGES - 1 < chunks) load_stage(c + GSTAGES - 1);

        const int s = c & (GSTAGES - 1);
        const uint32_t sa = sb + s * GSTAGE_B;
        const uint32_t sB = sa + GTILE_B;

        #pragma unroll
        for (int kk = 0; kk < 4; ++kk) {  // 4 k16 steps in BK=64
            // A frags: two m16 tiles
            uint32_t a[2][4];
            #pragma unroll
            for (int wm = 0; wm < 2; ++wm) {
                const int row = wr * 32 + wm * 16 + lrow;
                const uint32_t off = SWZ(row * 128 + (kk * 2 + lhalf) * 16);
                ldm_x4(a[wm][0], a[wm][1], a[wm][2], a[wm][3], sa + off);
            }
            // B frags: four n16 groups
            uint32_t b[4][4];
            #pragma unroll
            for (int g = 0; g < 4; ++g) {
                const int row = wc * 64 + g * 16 + lrow;
                const uint32_t off = SWZ(row * 128 + (kk * 2 + lhalf) * 16);
                ldm_x4(b[g][0], b[g][1], b[g][2], b[g][3], sB + off);
            }
            #pragma unroll
            for (int wm = 0; wm < 2; ++wm)
                #pragma unroll
                for (int j = 0; j < 8; ++j) {
                    const int g = j >> 1, h = j & 1;
                    mma16816(acc[wm][j][0], acc[wm][j][1], acc[wm][j][2], acc[wm][j][3],
                             a[wm][0], a[wm][1], a[wm][2], a[wm][3],
                             b[g][h], b[g][2 + h]);
                }
        }
    }

    // ---------------- epilogue: registers -> gmem ------------------------------
    const int tq = lid >> 2;    // 0..7 row-in-8
    const int tr = lid & 3;     // col pair
    const int H = N >> 1;
    #pragma unroll
    for (int wm = 0; wm < 2; ++wm) {
        #pragma unroll
        for (int j = 0; j < 8; ++j) {
            #pragma unroll
            for (int half = 0; half < 2; ++half) {
                const int gr = m0 + wr * 32 + wm * 16 + tq + half * 8;
                const int gc = n0 + wc * 64 + j * 8 + tr * 2;
                float v0 = acc[wm][j][half * 2 + 0];
                float v1 = acc[wm][j][half * 2 + 1];
                if (EPI == EPI_PLAIN) {
                    float2 v = {v0, v1};
                    *(float2*)&O0[(size_t)gr * N + gc] = v;
                } else if (EPI == EPI_SPLIT) {
                    float2 v = {v0, v1};
                    if (gc < H) *(float2*)&O0[(size_t)gr * H + gc] = v;
                    else        *(float2*)&O1[(size_t)gr * H + (gc - H)] = v;
                } else if (EPI == EPI_SOFTPLUS) {
                    v0 += bias[gc]; v1 += bias[gc + 1];
                    v0 = (v0 > 20.0f) ? v0 : log1pf(__expf(v0));
                    v1 = (v1 > 20.0f) ? v1 : log1pf(__expf(v1));
                    float2 v = {v0, v1};
                    *(float2*)&O0[(size_t)gr * N + gc] = v;
                } else { // EPI_XPROJ: 0..63 dtr | 64..79 Bm | 80..95 Cm | pad
                    float2 v = {v0, v1};
                    if (gc < DT_RANK)           *(float2*)&O0[(size_t)gr * DT_RANK + gc] = v;
                    else if (gc < DT_RANK + 16) *(float2*)&O1[(size_t)gr * 16 + (gc - DT_RANK)] = v;
                    else if (gc < DT_RANK + 32) *(float2*)&O2[(size_t)gr * 16 + (gc - DT_RANK - 16)] = v;
                }
            }
        }
    }
}

// ---------------- packing kernels ---------------------------------------------
__global__ __launch_bounds__(256)
void packA_kernel(const float* __restrict__ in, __nv_bfloat16* __restrict__ out, int K)
{
    const int m = blockIdx.y;
    const int k = (blockIdx.x * 256 + threadIdx.x) * 2;
    if (k >= K) return;
    const float2 v = *(const float2*)(in + (size_t)m * K + k);
    const __nv_bfloat16 h0 = __float2bfloat16(v.x);
    const __nv_bfloat16 h1 = __float2bfloat16(v.y);
    const __nv_bfloat16 l0 = __float2bfloat16(v.x - __bfloat162float(h0));
    const __nv_bfloat16 l1 = __float2bfloat16(v.y - __bfloat162float(h1));
    __nv_bfloat16* op = out + (size_t)m * 3 * K;
    __nv_bfloat162 hh; hh.x = h0; hh.y = h1;
    __nv_bfloat162 ll; ll.x = l0; ll.y = l1;
    *(__nv_bfloat162*)(op + k)         = hh;
    *(__nv_bfloat162*)(op + K + k)     = hh;
    *(__nv_bfloat162*)(op + 2 * K + k) = ll;
}

__global__ __launch_bounds__(256)
void packBt_kernel(const float* __restrict__ in, __nv_bfloat16* __restrict__ out,
                   int K, int N, int Np)
{
    __shared__ float s[32][33];
    const int kb = blockIdx.x * 32, nb = blockIdx.y * 32;
    const int tx = threadIdx.x & 31, ty = threadIdx.x >> 5;
    #pragma unroll
    for (int r = 0; r < 32; r += 8) {
        const int k = kb + ty + r, n = nb + tx;
        s[ty + r][tx] = (k < K && n < N) ? in[(size_t)k * N + n] : 0.0f;
    }
    __syncthreads();
    #pragma unroll
    for (int r = 0; r < 32; r += 8) {
        const int n = nb + ty + r, k = kb + tx;
        if (n < Np && k < K) {
            const float v = s[tx][ty + r];
            const __nv_bfloat16 h = __float2bfloat16(v);
            const __nv_bfloat16 lo = __float2bfloat16(v - __bfloat162float(h));
            __nv_bfloat16* op = out + (size_t)n * 3 * K;
            op[k] = h; op[K + k] = lo; op[2 * K + k] = h;
        }
    }
}

// ---------------- causal depthwise conv (k=4) + SiLU --------------------------
__global__ __launch_bounds__(256)
void conv_silu_kernel(const float* __restrict__ u, const float* __restrict__ w,
                      const float* __restrict__ bias, float* __restrict__ uc)
{
    constexpr int CHUNK = 16;
    int gid = blockIdx.x * blockDim.x + threadIdx.x;
    int d = gid & (D_INNER - 1);
    int rest = gid >> 11;
    int b = rest & (BATCH - 1);
    int chunk = rest >> 2;
    int l0 = chunk * CHUNK;

    const float w0 = w[d * 4 + 0], w1 = w[d * 4 + 1],
                w2 = w[d * 4 + 2], w3 = w[d * 4 + 3];
    const float bb = bias[d];

    const size_t base = ((size_t)b * SEQLEN + l0) * D_INNER + d;
    const float* up = u + base;
    float* op = uc + base;

    float xm3, xm2, xm1;
    if (l0 == 0) { xm3 = 0.f; xm2 = 0.f; xm1 = 0.f; }
    else {
        xm3 = up[-3 * D_INNER];
        xm2 = up[-2 * D_INNER];
        xm1 = up[-1 * D_INNER];
    }
    #pragma unroll
    for (int i = 0; i < CHUNK; ++i) {
        float cur = up[(size_t)i * D_INNER];
        float v = fmaf(xm3, w0, fmaf(xm2, w1, fmaf(xm1, w2, fmaf(cur, w3, bb))));
        float s = v / (1.0f + __expf(-v));
        op[(size_t)i * D_INNER] = s;
        xm3 = xm2; xm2 = xm1; xm1 = cur;
    }
}

// ---------------- selective scan: 4 threads per (b,d) channel -----------------
__global__ __launch_bounds__(128)
void scan_kernel(const float* __restrict__ delta, const float* __restrict__ u,
                 const float* __restrict__ z, const float* __restrict__ Bm,
                 const float* __restrict__ Cm, const float* __restrict__ A_log,
                 const float* __restrict__ Dp, float* __restrict__ y)
{
    const int t = blockIdx.x * blockDim.x + threadIdx.x;
    const int sub = t & 3;
    const int ch = t >> 2;
    const int d = ch & (D_INNER - 1);
    const int b = ch >> 11;
    const int n0 = sub * 4;

    const float a0 = -__expf(A_log[d * D_STATE + n0 + 0]);
    const float a1 = -__expf(A_log[d * D_STATE + n0 + 1]);
    const float a2 = -__expf(A_log[d * D_STATE + n0 + 2]);
    const float a3 = -__expf(A_log[d * D_STATE + n0 + 3]);

    const bool fast =
        fabsf(a0 + (float)(n0 + 1)) < 1e-3f * (n0 + 1) &&
        fabsf(a1 + (float)(n0 + 2)) < 1e-3f * (n0 + 2) &&
        fabsf(a2 + (float)(n0 + 3)) < 1e-3f * (n0 + 3) &&
        fabsf(a3 + (float)(n0 + 4)) < 1e-3f * (n0 + 4);

    const size_t base = (size_t)b * SEQLEN * D_INNER + d;
    const float* dp = delta + base;
    const float* up = u + base;
    const float* zp = z + base;
    float* yp = y + base;
    const float4* Bp = (const float4*)Bm + (size_t)b * SEQLEN * 4 + sub;
    const float4* Cp = (const float4*)Cm + (size_t)b * SEQLEN * 4 + sub;
    const float Dd = Dp[d];

    float h0 = 0.f, h1 = 0.f, h2 = 0.f, h3 = 0.f;

    if (fast) {
        #pragma unroll 2
        for (int l = 0; l < SEQLEN; ++l) {
            const float dt = dp[(size_t)l * D_INNER];
            const float uu = up[(size_t)l * D_INNER];
            const float4 Bv = Bp[(size_t)l * 4];
            const float4 Cv = Cp[(size_t)l * 4];
            const float e  = __expf(-dt);
            const float e2 = e * e;
            const float e4 = e2 * e2;
            const float e8 = e4 * e4;
            float m = 1.f;
            if (sub & 1) m = e4;
            if (sub & 2) m *= e8;
            const float dA0 = m * e;
            const float dA1 = dA0 * e;
            const float dA2 = dA1 * e;
            const float dA3 = dA2 * e;
            const float xv = dt * uu;
            h0 = fmaf(h0, dA0, xv * Bv.x);
            h1 = fmaf(h1, dA1, xv * Bv.y);
            h2 = fmaf(h2, dA2, xv * Bv.z);
            h3 = fmaf(h3, dA3, xv * Bv.w);
            float yv = h0 * Cv.x + h1 * Cv.y + h2 * Cv.z + h3 * Cv.w;
            yv += __shfl_xor_sync(0xffffffffu, yv, 1);
            yv += __shfl_xor_sync(0xffffffffu, yv, 2);
            if (sub == 0) {
                const float zz = zp[(size_t)l * D_INNER];
                const float sz = zz / (1.0f + __expf(-zz));
                yp[(size_t)l * D_INNER] = (yv + uu * Dd) * sz;
            }
        }
    } else {
        #pragma unroll 2
        for (int l = 0; l < SEQLEN; ++l) {
            const float dt = dp[(size_t)l * D_INNER];
            const float uu = up[(size_t)l * D_INNER];
            const float4 Bv = Bp[(size_t)l * 4];
            const float4 Cv = Cp[(size_t)l * 4];
            const float dA0 = __expf(dt * a0);
            const float dA1 = __expf(dt * a1);
            const float dA2 = __expf(dt * a2);
            const float dA3 = __expf(dt * a3);
            const float xv = dt * uu;
            h0 = fmaf(h0, dA0, xv * Bv.x);
            h1 = fmaf(h1, dA1, xv * Bv.y);
            h2 = fmaf(h2, dA2, xv * Bv.z);
            h3 = fmaf(h3, dA3, xv * Bv.w);
            float yv = h0 * Cv.x + h1 * Cv.y + h2 * Cv.z + h3 * Cv.w;
            yv += __shfl_xor_sync(0xffffffffu, yv, 1);
            yv += __shfl_xor_sync(0xffffffffu, yv, 2);
            if (sub == 0) {
                const float zz = zp[(size_t)l * D_INNER];
                const float sz = zz / (1.0f + __expf(-zz));
                yp[(size_t)l * D_INNER] = (yv + uu * Dd) * sz;
            }
        }
    }
}

// ---------------- launch ------------------------------------------------------
extern "C" void kernel_launch(void* const* d_in, const int* in_sizes, int n_in,
                              void* d_out, int out_size)
{
    const float* x      = (const float*)d_in[0];
    const float* W_in   = (const float*)d_in[1];
    const float* conv_w = (const float*)d_in[2];
    const float* conv_b = (const float*)d_in[3];
    const float* W_xprj = (const float*)d_in[4];
    const float* W_dt   = (const float*)d_in[5];
    const float* b_dt   = (const float*)d_in[6];
    const float* A_log  = (const float*)d_in[7];
    const float* Dp     = (const float*)d_in[8];
    const float* W_out  = (const float*)d_in[9];
    float* out = (float*)d_out;

    float *u, *z, *uc, *delta, *yb, *dtr, *Bm, *Cm;
    cudaGetSymbolAddress((void**)&u,     g_u);
    cudaGetSymbolAddress((void**)&z,     g_z);
    cudaGetSymbolAddress((void**)&uc,    g_uc);
    cudaGetSymbolAddress((void**)&delta, g_delta);
    cudaGetSymbolAddress((void**)&yb,    g_y);
    cudaGetSymbolAddress((void**)&dtr,   g_dtr);
    cudaGetSymbolAddress((void**)&Bm,    g_Bm);
    cudaGetSymbolAddress((void**)&Cm,    g_Cm);

    __nv_bfloat16 *x2, *Win2, *uc2, *Wxp2, *dtr2, *Wdt2, *y2, *Wout2;
    cudaGetSymbolAddress((void**)&x2,    g_x2);
    cudaGetSymbolAddress((void**)&Win2,  g_Win2);
    cudaGetSymbolAddress((void**)&uc2,   g_uc2);
    cudaGetSymbolAddress((void**)&Wxp2,  g_Wxp2);
    cudaGetSymbolAddress((void**)&dtr2,  g_dtr2);
    cudaGetSymbolAddress((void**)&Wdt2,  g_Wdt2);
    cudaGetSymbolAddress((void**)&y2,    g_y2);
    cudaGetSymbolAddress((void**)&Wout2, g_Wout2);

    cudaFuncSetAttribute(gemm_tc<EPI_PLAIN>,   cudaFuncAttributeMaxDynamicSharedMemorySize, GEMM_SMEM);
    cudaFuncSetAttribute(gemm_tc<EPI_SPLIT>,   cudaFuncAttributeMaxDynamicSharedMemorySize, GEMM_SMEM);
    cudaFuncSetAttribute(gemm_tc<EPI_SOFTPLUS>,cudaFuncAttributeMaxDynamicSharedMemorySize, GEMM_SMEM);
    cudaFuncSetAttribute(gemm_tc<EPI_XPROJ>,   cudaFuncAttributeMaxDynamicSharedMemorySize, GEMM_SMEM);

    // ---- G1: xz = x @ W_in, split u|z --------------------------------------
    packA_kernel<<<dim3((D_MODEL / 2 + 255) / 256, ROWS), 256>>>(x, x2, D_MODEL);
    packBt_kernel<<<dim3(D_MODEL / 32, (2 * D_INNER) / 32), 256>>>(
        W_in, Win2, D_MODEL, 2 * D_INNER, 2 * D_INNER);
    gemm_tc<EPI_SPLIT><<<dim3((2 * D_INNER) / GBN, ROWS / GBM), 256, GEMM_SMEM>>>(
        x2, Win2, 3 * D_MODEL, 2 * D_INNER, u, z, nullptr, nullptr);

    // ---- conv + silu --------------------------------------------------------
    conv_silu_kernel<<<(BATCH * D_INNER * (SEQLEN / 16)) / 256, 256>>>(u, conv_w, conv_b, uc);

    // ---- G2: proj = uc @ W_xproj -> dtr|Bm|Cm (N padded 96->128) -----------
    packA_kernel<<<dim3((D_INNER / 2 + 255) / 256, ROWS), 256>>>(uc, uc2, D_INNER);
    packBt_kernel<<<dim3(D_INNER / 32, 128 / 32), 256>>>(
        W_xprj, Wxp2, D_INNER, DT_RANK + 2 * D_STATE, 128);
    gemm_tc<EPI_XPROJ><<<dim3(1, ROWS / GBM), 256, GEMM_SMEM>>>(
        uc2, Wxp2, 3 * D_INNER, 128, dtr, Bm, Cm, nullptr);

    // ---- G3: delta = softplus(dtr @ W_dt + b_dt) ---------------------------
    packA_kernel<<<dim3((DT_RANK / 2 + 255) / 256, ROWS), 256>>>(dtr, dtr2, DT_RANK);
    packBt_kernel<<<dim3((DT_RANK + 31) / 32, D_INNER / 32), 256>>>(
        W_dt, Wdt2, DT_RANK, D_INNER, D_INNER);
    gemm_tc<EPI_SOFTPLUS><<<dim3(D_INNER / GBN, ROWS / GBM), 256, GEMM_SMEM>>>(
        dtr2, Wdt2, 3 * DT_RANK, D_INNER, delta, nullptr, nullptr, b_dt);

    // ---- scan + gating ------------------------------------------------------
    scan_kernel<<<(ROWS * 4) / 128, 128>>>(delta, uc, z, Bm, Cm, A_log, Dp, yb);

    // ---- G5: out = y @ W_out ------------------------------------------------
    packA_kernel<<<dim3((D_INNER / 2 + 255) / 256, ROWS), 256>>>(yb, y2, D_INNER);
    packBt_kernel<<<dim3(D_INNER / 32, D_MODEL / 32), 256>>>(
        W_out, Wout2, D_INNER, D_MODEL, D_MODEL);
    gemm_tc<EPI_PLAIN><<<dim3(D_MODEL / GBN, ROWS / GBM), 256, GEMM_SMEM>>>(
        y2, Wout2, 3 * D_INNER, D_MODEL, out, nullptr, nullptr, nullptr);
}

// round 4
// speedup vs baseline: 1.4572x; 1.0115x over previous
#include <cuda_runtime.h>
#include <cuda_bf16.h>
#include <cstdint>
#include <math.h>

#define D_MODEL 1024
#define D_STATE 16
#define D_INNER 2048
#define DT_RANK 64
#define BATCH   4
#define SEQLEN  2048
#define ROWS    (BATCH * SEQLEN)   // 8192

// ---------------- device scratch (allocation-free rule) -----------------------
__device__ __align__(16) float g_u[ROWS * D_INNER];
__device__ __align__(16) float g_z[ROWS * D_INNER];
__device__ __align__(16) float g_uc[ROWS * D_INNER];
__device__ __align__(16) float g_delta[ROWS * D_INNER];
__device__ __align__(16) float g_dtr[ROWS * DT_RANK];
__device__ __align__(16) float g_Bm[ROWS * D_STATE];
__device__ __align__(16) float g_Cm[ROWS * D_STATE];

// packed bf16 operands (hi|hi|lo along K for A; hi|lo|hi for B^T)
__device__ __align__(16) __nv_bfloat16 g_x2  [ROWS * 3 * D_MODEL];
__device__ __align__(16) __nv_bfloat16 g_Win2[(2*D_INNER) * 3 * D_MODEL];
__device__ __align__(16) __nv_bfloat16 g_uc2 [ROWS * 3 * D_INNER];
__device__ __align__(16) __nv_bfloat16 g_Wxp2[128 * 3 * D_INNER];
__device__ __align__(16) __nv_bfloat16 g_dtr2[ROWS * 3 * DT_RANK];
__device__ __align__(16) __nv_bfloat16 g_Wdt2[D_INNER * 3 * DT_RANK];
__device__ __align__(16) __nv_bfloat16 g_y2  [ROWS * 3 * D_INNER];
__device__ __align__(16) __nv_bfloat16 g_Wout2[D_MODEL * 3 * D_INNER];

// ---------------- helpers -----------------------------------------------------
__device__ __forceinline__ uint32_t smem_u32(const void* p) {
    uint32_t a;
    asm("{ .reg .u64 t; cvta.to.shared.u64 t, %1; cvt.u32.u64 %0, t; }" : "=r"(a) : "l"(p));
    return a;
}
__device__ __forceinline__ void cp16(uint32_t saddr, const void* gaddr) {
    asm volatile("cp.async.cg.shared.global [%0], [%1], 16;" :: "r"(saddr), "l"(gaddr));
}
#define SWZ(o) ((o) ^ ((((uint32_t)(o)) >> 3) & 0x70))

__device__ __forceinline__ void ldm_x4(uint32_t& r0, uint32_t& r1, uint32_t& r2, uint32_t& r3,
                                       uint32_t addr) {
    asm volatile("ldmatrix.sync.aligned.m8n8.x4.shared.b16 {%0,%1,%2,%3}, [%4];"
                 : "=r"(r0), "=r"(r1), "=r"(r2), "=r"(r3) : "r"(addr));
}
__device__ __forceinline__ void mma16816(float& c0, float& c1, float& c2, float& c3,
                                         uint32_t a0, uint32_t a1, uint32_t a2, uint32_t a3,
                                         uint32_t b0, uint32_t b1) {
    asm volatile("mma.sync.aligned.m16n8k16.row.col.f32.bf16.bf16.f32 "
                 "{%0,%1,%2,%3}, {%4,%5,%6,%7}, {%8,%9}, {%0,%1,%2,%3};"
                 : "+f"(c0), "+f"(c1), "+f"(c2), "+f"(c3)
                 : "r"(a0), "r"(a1), "r"(a2), "r"(a3), "r"(b0), "r"(b1));
}
__device__ __forceinline__ void split_bf16(float v, __nv_bfloat16& h, __nv_bfloat16& l) {
    h = __float2bfloat16(v);
    l = __float2bfloat16(v - __bfloat162float(h));
}

// ---------------- bf16 mma.sync GEMM ------------------------------------------
enum { EPI_PLAIN = 0, EPI_SPLIT = 1, EPI_SOFTPLUS = 2, EPI_XPROJ = 3 };

#define GBM 128
#define GBN 128
#define GBK 64
#define GSTAGES 3
#define GTILE_B (GBM * GBK * 2)          // 16384 bytes per operand tile
#define GSTAGE_B (2 * GTILE_B)           // 32768
#define GEMM_SMEM (GSTAGES * GSTAGE_B)   // 98304

template <int EPI>
__global__ __launch_bounds__(256, 2)
void gemm_tc(const __nv_bfloat16* __restrict__ A, const __nv_bfloat16* __restrict__ Bt,
             int Kp, int N,
             float* __restrict__ O0, float* __restrict__ O1, float* __restrict__ O2,
             const float* __restrict__ bias)
{
    extern __shared__ char smem[];
    const uint32_t sb = smem_u32(smem);
    const int tid = threadIdx.x;
    const int wid = tid >> 5, lid = tid & 31;
    const int wr = wid & 3;
    const int wc = wid >> 2;
    const int m0 = blockIdx.y * GBM;
    const int n0 = blockIdx.x * GBN;
    const int chunks = Kp / GBK;

    const __nv_bfloat16* Ap = A + (size_t)m0 * Kp;
    const __nv_bfloat16* Bp = Bt + (size_t)n0 * Kp;

    const int ldrow = tid >> 3;
    const int ldch  = tid & 7;

    auto load_stage = [&](int c) {
        const int s = c % GSTAGES;
        const uint32_t sa = sb + s * GSTAGE_B;
        const uint32_t sB = sa + GTILE_B;
        const int k0 = c * GBK;
        #pragma unroll
        for (int j = 0; j < 4; ++j) {
            const int r = ldrow + j * 32;
            const uint32_t so = SWZ(r * 128 + ldch * 16);
            cp16(sa + so, Ap + (size_t)r * Kp + k0 + ldch * 8);
            cp16(sB + so, Bp + (size_t)r * Kp + k0 + ldch * 8);
        }
        asm volatile("cp.async.commit_group;" ::: "memory");
    };

    const int pre = (chunks < GSTAGES - 1) ? chunks : (GSTAGES - 1);
    for (int c = 0; c < pre; ++c) load_stage(c);

    float acc[2][8][4];
    #pragma unroll
    for (int i = 0; i < 2; ++i)
        #pragma unroll
        for (int j = 0; j < 8; ++j)
            #pragma unroll
            for (int k = 0; k < 4; ++k) acc[i][j][k] = 0.f;

    const int lrow = lid & 15;
    const int lhalf = lid >> 4;

    for (int c = 0; c < chunks; ++c) {
        const int remaining = chunks - 1 - c;
        if (remaining >= 1) asm volatile("cp.async.wait_group 1;" ::: "memory");
        else                asm volatile("cp.async.wait_group 0;" ::: "memory");
        __syncthreads();

        if (c + GSTAGES - 1 < chunks) load_stage(c + GSTAGES - 1);

        const int s = c % GSTAGES;
        const uint32_t sa = sb + s * GSTAGE_B;
        const uint32_t sB = sa + GTILE_B;

        #pragma unroll
        for (int kk = 0; kk < 4; ++kk) {
            uint32_t a[2][4];
            #pragma unroll
            for (int wm = 0; wm < 2; ++wm) {
                const int row = wr * 32 + wm * 16 + lrow;
                const uint32_t off = SWZ(row * 128 + (kk * 2 + lhalf) * 16);
                ldm_x4(a[wm][0], a[wm][1], a[wm][2], a[wm][3], sa + off);
            }
            uint32_t b[4][4];
            #pragma unroll
            for (int g = 0; g < 4; ++g) {
                const int row = wc * 64 + g * 16 + lrow;
                const uint32_t off = SWZ(row * 128 + (kk * 2 + lhalf) * 16);
                ldm_x4(b[g][0], b[g][1], b[g][2], b[g][3], sB + off);
            }
            #pragma unroll
            for (int wm = 0; wm < 2; ++wm)
                #pragma unroll
                for (int j = 0; j < 8; ++j) {
                    const int g = j >> 1, h = j & 1;
                    mma16816(acc[wm][j][0], acc[wm][j][1], acc[wm][j][2], acc[wm][j][3],
                             a[wm][0], a[wm][1], a[wm][2], a[wm][3],
                             b[g][h], b[g][2 + h]);
                }
        }
    }

    // ---------------- epilogue ------------------------------------------------
    const int tq = lid >> 2;
    const int tr = lid & 3;
    const int H = N >> 1;
    #pragma unroll
    for (int wm = 0; wm < 2; ++wm) {
        #pragma unroll
        for (int j = 0; j < 8; ++j) {
            #pragma unroll
            for (int half = 0; half < 2; ++half) {
                const int gr = m0 + wr * 32 + wm * 16 + tq + half * 8;
                const int gc = n0 + wc * 64 + j * 8 + tr * 2;
                float v0 = acc[wm][j][half * 2 + 0];
                float v1 = acc[wm][j][half * 2 + 1];
                if (EPI == EPI_PLAIN) {
                    float2 v = {v0, v1};
                    *(float2*)&O0[(size_t)gr * N + gc] = v;
                } else if (EPI == EPI_SPLIT) {
                    float2 v = {v0, v1};
                    if (gc < H) *(float2*)&O0[(size_t)gr * H + gc] = v;
                    else        *(float2*)&O1[(size_t)gr * H + (gc - H)] = v;
                } else if (EPI == EPI_SOFTPLUS) {
                    v0 += bias[gc]; v1 += bias[gc + 1];
                    v0 = (v0 > 20.0f) ? v0 : log1pf(__expf(v0));
                    v1 = (v1 > 20.0f) ? v1 : log1pf(__expf(v1));
                    float2 v = {v0, v1};
                    *(float2*)&O0[(size_t)gr * N + gc] = v;
                } else { // EPI_XPROJ
                    float2 v = {v0, v1};
                    if (gc < DT_RANK)           *(float2*)&O0[(size_t)gr * DT_RANK + gc] = v;
                    else if (gc < DT_RANK + 16) *(float2*)&O1[(size_t)gr * 16 + (gc - DT_RANK)] = v;
                    else if (gc < DT_RANK + 32) *(float2*)&O2[(size_t)gr * 16 + (gc - DT_RANK - 16)] = v;
                }
            }
        }
    }
}

// ---------------- packing kernels ---------------------------------------------
__global__ __launch_bounds__(256)
void packA_kernel(const float* __restrict__ in, __nv_bfloat16* __restrict__ out, int K)
{
    const int m = blockIdx.y;
    const int k = (blockIdx.x * 256 + threadIdx.x) * 2;
    if (k >= K) return;
    const float2 v = *(const float2*)(in + (size_t)m * K + k);
    __nv_bfloat16 h0, h1, l0, l1;
    split_bf16(v.x, h0, l0);
    split_bf16(v.y, h1, l1);
    __nv_bfloat16* op = out + (size_t)m * 3 * K;
    __nv_bfloat162 hh; hh.x = h0; hh.y = h1;
    __nv_bfloat162 ll; ll.x = l0; ll.y = l1;
    *(__nv_bfloat162*)(op + k)         = hh;
    *(__nv_bfloat162*)(op + K + k)     = hh;
    *(__nv_bfloat162*)(op + 2 * K + k) = ll;
}

__global__ __launch_bounds__(256)
void packBt_kernel(const float* __restrict__ in, __nv_bfloat16* __restrict__ out,
                   int K, int N, int Np)
{
    __shared__ float s[32][33];
    const int kb = blockIdx.x * 32, nb = blockIdx.y * 32;
    const int tx = threadIdx.x & 31, ty = threadIdx.x >> 5;
    #pragma unroll
    for (int r = 0; r < 32; r += 8) {
        const int k = kb + ty + r, n = nb + tx;
        s[ty + r][tx] = (k < K && n < N) ? in[(size_t)k * N + n] : 0.0f;
    }
    __syncthreads();
    #pragma unroll
    for (int r = 0; r < 32; r += 8) {
        const int n = nb + ty + r, k = kb + tx;
        if (n < Np && k < K) {
            const float v = s[tx][ty + r];
            __nv_bfloat16 h, lo;
            split_bf16(v, h, lo);
            __nv_bfloat16* op = out + (size_t)n * 3 * K;
            op[k] = h; op[K + k] = lo; op[2 * K + k] = h;
        }
    }
}

// ---------------- causal depthwise conv (k=4) + SiLU + pack -------------------
__global__ __launch_bounds__(256)
void conv_silu_kernel(const float* __restrict__ u, const float* __restrict__ w,
                      const float* __restrict__ bias, float* __restrict__ uc,
                      __nv_bfloat16* __restrict__ uc2)
{
    constexpr int CHUNK = 16;
    int gid = blockIdx.x * blockDim.x + threadIdx.x;
    int d = gid & (D_INNER - 1);
    int rest = gid >> 11;
    int b = rest & (BATCH - 1);
    int chunk = rest >> 2;
    int l0 = chunk * CHUNK;

    const float w0 = w[d * 4 + 0], w1 = w[d * 4 + 1],
                w2 = w[d * 4 + 2], w3 = w[d * 4 + 3];
    const float bb = bias[d];

    const size_t base = ((size_t)b * SEQLEN + l0) * D_INNER + d;
    const float* up = u + base;
    float* op = uc + base;
    __nv_bfloat16* pp = uc2 + ((size_t)b * SEQLEN + l0) * 3 * D_INNER + d;

    float xm3, xm2, xm1;
    if (l0 == 0) { xm3 = 0.f; xm2 = 0.f; xm1 = 0.f; }
    else {
        xm3 = up[-3 * D_INNER];
        xm2 = up[-2 * D_INNER];
        xm1 = up[-1 * D_INNER];
    }
    #pragma unroll
    for (int i = 0; i < CHUNK; ++i) {
        float cur = up[(size_t)i * D_INNER];
        float v = fmaf(xm3, w0, fmaf(xm2, w1, fmaf(xm1, w2, fmaf(cur, w3, bb))));
        float s = v / (1.0f + __expf(-v));
        op[(size_t)i * D_INNER] = s;
        __nv_bfloat16 h, lo;
        split_bf16(s, h, lo);
        __nv_bfloat16* q = pp + (size_t)i * 3 * D_INNER;
        q[0] = h; q[D_INNER] = h; q[2 * D_INNER] = lo;
        xm3 = xm2; xm2 = xm1; xm1 = cur;
    }
}

// ---------------- selective scan ----------------------------------------------
__global__ __launch_bounds__(128)
void scan_kernel(const float* __restrict__ delta, const float* __restrict__ u,
                 const float* __restrict__ z, const float* __restrict__ Bm,
                 const float* __restrict__ Cm, const float* __restrict__ A_log,
                 const float* __restrict__ Dp, __nv_bfloat16* __restrict__ y2)
{
    const int t = blockIdx.x * blockDim.x + threadIdx.x;
    const int sub = t & 3;
    const int ch = t >> 2;
    const int d = ch & (D_INNER - 1);
    const int b = ch >> 11;
    const int n0 = sub * 4;

    const float a0 = -__expf(A_log[d * D_STATE + n0 + 0]);
    const float a1 = -__expf(A_log[d * D_STATE + n0 + 1]);
    const float a2 = -__expf(A_log[d * D_STATE + n0 + 2]);
    const float a3 = -__expf(A_log[d * D_STATE + n0 + 3]);

    const bool fast =
        fabsf(a0 + (float)(n0 + 1)) < 1e-3f * (n0 + 1) &&
        fabsf(a1 + (float)(n0 + 2)) < 1e-3f * (n0 + 2) &&
        fabsf(a2 + (float)(n0 + 3)) < 1e-3f * (n0 + 3) &&
        fabsf(a3 + (float)(n0 + 4)) < 1e-3f * (n0 + 4);

    const size_t base = (size_t)b * SEQLEN * D_INNER + d;
    const float* dp = delta + base;
    const float* up = u + base;
    const float* zp = z + base;
    __nv_bfloat16* yp = y2 + (size_t)b * SEQLEN * 3 * D_INNER + d;
    const float4* Bp = (const float4*)Bm + (size_t)b * SEQLEN * 4 + sub;
    const float4* Cp = (const float4*)Cm + (size_t)b * SEQLEN * 4 + sub;
    const float Dd = Dp[d];

    float h0 = 0.f, h1 = 0.f, h2 = 0.f, h3 = 0.f;

    if (fast) {
        #pragma unroll 2
        for (int l = 0; l < SEQLEN; ++l) {
            const float dt = dp[(size_t)l * D_INNER];
            const float uu = up[(size_t)l * D_INNER];
            const float4 Bv = Bp[(size_t)l * 4];
            const float4 Cv = Cp[(size_t)l * 4];
            const float e  = __expf(-dt);
            const float e2 = e * e;
            const float e4 = e2 * e2;
            const float e8 = e4 * e4;
            float m = 1.f;
            if (sub & 1) m = e4;
            if (sub & 2) m *= e8;
            const float dA0 = m * e;
            const float dA1 = dA0 * e;
            const float dA2 = dA1 * e;
            const float dA3 = dA2 * e;
            const float xv = dt * uu;
            h0 = fmaf(h0, dA0, xv * Bv.x);
            h1 = fmaf(h1, dA1, xv * Bv.y);
            h2 = fmaf(h2, dA2, xv * Bv.z);
            h3 = fmaf(h3, dA3, xv * Bv.w);
            float yv = h0 * Cv.x + h1 * Cv.y + h2 * Cv.z + h3 * Cv.w;
            yv += __shfl_xor_sync(0xffffffffu, yv, 1);
            yv += __shfl_xor_sync(0xffffffffu, yv, 2);
            if (sub == 0) {
                const float zz = zp[(size_t)l * D_INNER];
                const float sz = zz / (1.0f + __expf(-zz));
                const float yo = (yv + uu * Dd) * sz;
                __nv_bfloat16 h, lo;
                split_bf16(yo, h, lo);
                __nv_bfloat16* q = yp + (size_t)l * 3 * D_INNER;
                q[0] = h; q[D_INNER] = h; q[2 * D_INNER] = lo;
            }
        }
    } else {
        #pragma unroll 2
        for (int l = 0; l < SEQLEN; ++l) {
            const float dt = dp[(size_t)l * D_INNER];
            const float uu = up[(size_t)l * D_INNER];
            const float4 Bv = Bp[(size_t)l * 4];
            const float4 Cv = Cp[(size_t)l * 4];
            const float dA0 = __expf(dt * a0);
            const float dA1 = __expf(dt * a1);
            const float dA2 = __expf(dt * a2);
            const float dA3 = __expf(dt * a3);
            const float xv = dt * uu;
            h0 = fmaf(h0, dA0, xv * Bv.x);
            h1 = fmaf(h1, dA1, xv * Bv.y);
            h2 = fmaf(h2, dA2, xv * Bv.z);
            h3 = fmaf(h3, dA3, xv * Bv.w);
            float yv = h0 * Cv.x + h1 * Cv.y + h2 * Cv.z + h3 * Cv.w;
            yv += __shfl_xor_sync(0xffffffffu, yv, 1);
            yv += __shfl_xor_sync(0xffffffffu, yv, 2);
            if (sub == 0) {
                const float zz = zp[(size_t)l * D_INNER];
                const float sz = zz / (1.0f + __expf(-zz));
                const float yo = (yv + uu * Dd) * sz;
                __nv_bfloat16 h, lo;
                split_bf16(yo, h, lo);
                __nv_bfloat16* q = yp + (size_t)l * 3 * D_INNER;
                q[0] = h; q[D_INNER] = h; q[2 * D_INNER] = lo;
            }
        }
    }
}

// ---------------- launch ------------------------------------------------------
extern "C" void kernel_launch(void* const* d_in, const int* in_sizes, int n_in,
                              void* d_out, int out_size)
{
    const float* x      = (const float*)d_in[0];
    const float* W_in   = (const float*)d_in[1];
    const float* conv_w = (const float*)d_in[2];
    const float* conv_b = (const float*)d_in[3];
    const float* W_xprj = (const float*)d_in[4];
    const float* W_dt   = (const float*)d_in[5];
    const float* b_dt   = (const float*)d_in[6];
    const float* A_log  = (const float*)d_in[7];
    const float* Dp     = (const float*)d_in[8];
    const float* W_out  = (const float*)d_in[9];
    float* out = (float*)d_out;

    float *u, *z, *uc, *delta, *dtr, *Bm, *Cm;
    cudaGetSymbolAddress((void**)&u,     g_u);
    cudaGetSymbolAddress((void**)&z,     g_z);
    cudaGetSymbolAddress((void**)&uc,    g_uc);
    cudaGetSymbolAddress((void**)&delta, g_delta);
    cudaGetSymbolAddress((void**)&dtr,   g_dtr);
    cudaGetSymbolAddress((void**)&Bm,    g_Bm);
    cudaGetSymbolAddress((void**)&Cm,    g_Cm);

    __nv_bfloat16 *x2, *Win2, *uc2, *Wxp2, *dtr2, *Wdt2, *y2, *Wout2;
    cudaGetSymbolAddress((void**)&x2,    g_x2);
    cudaGetSymbolAddress((void**)&Win2,  g_Win2);
    cudaGetSymbolAddress((void**)&uc2,   g_uc2);
    cudaGetSymbolAddress((void**)&Wxp2,  g_Wxp2);
    cudaGetSymbolAddress((void**)&dtr2,  g_dtr2);
    cudaGetSymbolAddress((void**)&Wdt2,  g_Wdt2);
    cudaGetSymbolAddress((void**)&y2,    g_y2);
    cudaGetSymbolAddress((void**)&Wout2, g_Wout2);

    cudaFuncSetAttribute(gemm_tc<EPI_PLAIN>,   cudaFuncAttributeMaxDynamicSharedMemorySize, GEMM_SMEM);
    cudaFuncSetAttribute(gemm_tc<EPI_SPLIT>,   cudaFuncAttributeMaxDynamicSharedMemorySize, GEMM_SMEM);
    cudaFuncSetAttribute(gemm_tc<EPI_SOFTPLUS>,cudaFuncAttributeMaxDynamicSharedMemorySize, GEMM_SMEM);
    cudaFuncSetAttribute(gemm_tc<EPI_XPROJ>,   cudaFuncAttributeMaxDynamicSharedMemorySize, GEMM_SMEM);

    // weight packs up front (independent of activations)
    packBt_kernel<<<dim3(D_MODEL / 32, (2 * D_INNER) / 32), 256>>>(
        W_in, Win2, D_MODEL, 2 * D_INNER, 2 * D_INNER);
    packBt_kernel<<<dim3(D_INNER / 32, 128 / 32), 256>>>(
        W_xprj, Wxp2, D_INNER, DT_RANK + 2 * D_STATE, 128);
    packBt_kernel<<<dim3((DT_RANK + 31) / 32, D_INNER / 32), 256>>>(
        W_dt, Wdt2, DT_RANK, D_INNER, D_INNER);
    packBt_kernel<<<dim3(D_INNER / 32, D_MODEL / 32), 256>>>(
        W_out, Wout2, D_INNER, D_MODEL, D_MODEL);

    // ---- G1: xz = x @ W_in, split u|z --------------------------------------
    packA_kernel<<<dim3((D_MODEL / 2 + 255) / 256, ROWS), 256>>>(x, x2, D_MODEL);
    gemm_tc<EPI_SPLIT><<<dim3((2 * D_INNER) / GBN, ROWS / GBM), 256, GEMM_SMEM>>>(
        x2, Win2, 3 * D_MODEL, 2 * D_INNER, u, z, nullptr, nullptr);

    // ---- conv + silu + pack uc2 --------------------------------------------
    conv_silu_kernel<<<(BATCH * D_INNER * (SEQLEN / 16)) / 256, 256>>>(
        u, conv_w, conv_b, uc, uc2);

    // ---- G2: proj = uc @ W_xproj -> dtr|Bm|Cm ------------------------------
    gemm_tc<EPI_XPROJ><<<dim3(1, ROWS / GBM), 256, GEMM_SMEM>>>(
        uc2, Wxp2, 3 * D_INNER, 128, dtr, Bm, Cm, nullptr);

    // ---- G3: delta = softplus(dtr @ W_dt + b_dt) ---------------------------
    packA_kernel<<<dim3((DT_RANK / 2 + 255) / 256, ROWS), 256>>>(dtr, dtr2, DT_RANK);
    gemm_tc<EPI_SOFTPLUS><<<dim3(D_INNER / GBN, ROWS / GBM), 256, GEMM_SMEM>>>(
        dtr2, Wdt2, 3 * DT_RANK, D_INNER, delta, nullptr, nullptr, b_dt);

    // ---- scan + gating -> packed y2 ----------------------------------------
    scan_kernel<<<(ROWS * 4) / 128, 128>>>(delta, uc, z, Bm, Cm, A_log, Dp, y2);

    // ---- G5: out = y @ W_out ------------------------------------------------
    gemm_tc<EPI_PLAIN><<<dim3(D_MODEL / GBN, ROWS / GBM), 256, GEMM_SMEM>>>(
        y2, Wout2, 3 * D_INNER, D_MODEL, out, nullptr, nullptr, nullptr);
}